// round 16
// baseline (speedup 1.0000x reference)
#include <cuda_runtime.h>
#include <cstdint>

// FixBatchChebConv: B=8, N=50000, Cin=Cout=64, K=3, E=400000
#define BB    8
#define NN    50000
#define EE    400000
#define FF    512           // BB*64, features per node in transposed layout
#define FF4   (FF/4)

#define GEMM_BLOCKS 1563    // ceil(50000/32)
#define SPMM_BLOCKS 6250    // 50000 rows / 8 warps
#define FAT_BLOCKS  (GEMM_BLOCKS + SPMM_BLOCKS)   // 7813; gemm bids: bid%5==2 (exactly 1563)

// ---------------- scratch (static device globals; no runtime allocation) ----
__device__ float g_t1[(size_t)NN * FF];   // tx1 = L @ x    (transposed [n][512])
__device__ float g_u [(size_t)NN * FF];   // u   = L @ tx1  (t2 = 2u - x folded into W)
__device__ float g_wt[12288];             // folded weights: [W0-W2 | W1 | 2*W2], [t][ci][co]
__device__ int   g_deg[NN];
__device__ int   g_rowstart[NN];
__device__ int   g_fill[NN];
__device__ float g_dinv[NN];
__device__ int   g_col[EE];
__device__ float g_lap[EE];
__device__ int   g_total;
__device__ int   g_is64;

// ---------------- setup kernels ---------------------------------------------
__global__ void k_setup1(const void* ei, const float* __restrict__ wgt) {
    int n = blockIdx.x * blockDim.x + threadIdx.x;
    if (n < NN) { g_deg[n] = 0; g_fill[n] = 0; }
    if (n == 0) g_total = 0;
    if (n < 12288) {
        int t = n >> 12;                 // 0..2
        float w = wgt[n];
        if (t == 0)      w = w - wgt[n + 8192];   // W0 - W2
        else if (t == 2) w = 2.0f * w;            // 2*W2
        g_wt[n] = w;
    }
    if (blockIdx.x == 0 && threadIdx.x < 64) {
        const long long* p = (const long long*)ei;
        long long v = p[threadIdx.x];
        int ok = (v >= 0 && v < NN) ? 1 : 0;
        unsigned m0 = __ballot_sync(0xffffffffu, ok);
        __shared__ unsigned warp_ok[2];
        if ((threadIdx.x & 31) == 0) warp_ok[threadIdx.x >> 5] = m0;
        __syncthreads();
        if (threadIdx.x == 0)
            g_is64 = (warp_ok[0] == 0xffffffffu && warp_ok[1] == 0xffffffffu) ? 1 : 0;
    }
}

__device__ __forceinline__ void load_edge(const void* ei, int e, int& r, int& c) {
    if (g_is64) {
        const long long* p = (const long long*)ei;
        r = (int)p[e]; c = (int)p[EE + e];
    } else {
        const int* p = (const int*)ei;
        r = p[e]; c = p[EE + e];
    }
}

__global__ void k_count(const void* ei) {
    int e = blockIdx.x * blockDim.x + threadIdx.x;
    if (e >= EE) return;
    int r, c; load_edge(ei, e, r, c);
    if (r != c) atomicAdd(&g_deg[r], 1);
}

__global__ void k_setup2() {
    int n = blockIdx.x * blockDim.x + threadIdx.x;
    int lane = threadIdx.x & 31;
    int d = (n < NN) ? g_deg[n] : 0;
    if (n < NN) g_dinv[n] = (d > 0) ? rsqrtf((float)d) : 0.0f;
    int incl = d;
    #pragma unroll
    for (int o = 1; o < 32; o <<= 1) {
        int y = __shfl_up_sync(0xffffffffu, incl, o);
        if (lane >= o) incl += y;
    }
    int tot = __shfl_sync(0xffffffffu, incl, 31);
    int base = 0;
    if (lane == 0) base = atomicAdd(&g_total, tot);
    base = __shfl_sync(0xffffffffu, base, 0);
    if (n < NN) g_rowstart[n] = base + incl - d;
}

__global__ void k_fill(const void* ei) {
    int e = blockIdx.x * blockDim.x + threadIdx.x;
    if (e >= EE) return;
    int r, c; load_edge(ei, e, r, c);
    if (r != c) {
        int pos = atomicAdd(&g_fill[r], 1);
        int idx = g_rowstart[r] + pos;
        g_col[idx] = c;
        g_lap[idx] = -g_dinv[r] * g_dinv[c];
    }
}

// ---------------- spmm bodies (one warp per row) -----------------------------
__device__ __forceinline__ void spmm0_body(int gw, int lane,
                                           const float* __restrict__ x) {
    int s = g_rowstart[gw];
    int e = s + g_deg[gw];
    int c4 = lane & 15;
    int b0 = lane >> 4;
    float4 acc[4];
    #pragma unroll
    for (int q = 0; q < 4; q++) acc[q] = make_float4(0.f, 0.f, 0.f, 0.f);
    const float4* xv = (const float4*)x;
    for (int i = s; i < e; i++) {
        int   c = g_col[i];
        float w = g_lap[i];
        #pragma unroll
        for (int q = 0; q < 4; q++) {
            float4 v = __ldg(&xv[((size_t)(b0 + q * 2) * NN + c) * 16 + c4]);
            acc[q].x += w * v.x; acc[q].y += w * v.y;
            acc[q].z += w * v.z; acc[q].w += w * v.w;
        }
    }
    float4* dstv = (float4*)g_t1;
    size_t o0 = (size_t)gw * FF4 + lane;
    #pragma unroll
    for (int q = 0; q < 4; q++) dstv[o0 + q * 32] = acc[q];
}

__device__ __forceinline__ void spmm1_body(int gw, int lane) {
    int s = g_rowstart[gw];
    int e = s + g_deg[gw];
    float4 acc[4];
    #pragma unroll
    for (int q = 0; q < 4; q++) acc[q] = make_float4(0.f, 0.f, 0.f, 0.f);
    const float4* srcv = (const float4*)g_t1;
    for (int i = s; i < e; i++) {
        int   c = g_col[i];
        float w = g_lap[i];
        size_t b0 = (size_t)c * FF4 + lane;
        #pragma unroll
        for (int q = 0; q < 4; q++) {
            float4 v = __ldg(&srcv[b0 + q * 32]);
            acc[q].x += w * v.x; acc[q].y += w * v.y;
            acc[q].z += w * v.z; acc[q].w += w * v.w;
        }
    }
    float4* dstv = (float4*)g_u;
    size_t o0 = (size_t)gw * FF4 + lane;
    #pragma unroll
    for (int q = 0; q < 4; q++) dstv[o0 + q * 32] = acc[q];
}

// ---------------- packed f32x2 helpers --------------------------------------
__device__ __forceinline__ unsigned long long pack2(float f) {
    unsigned long long d;
    unsigned u = __float_as_uint(f);
    asm("mov.b64 %0, {%1, %1};" : "=l"(d) : "r"(u));
    return d;
}
__device__ __forceinline__ void unpack2(unsigned long long v, float& lo, float& hi) {
    unsigned a, b;
    asm("mov.b64 {%0, %1}, %2;" : "=r"(a), "=r"(b) : "l"(v));
    lo = __uint_as_float(a); hi = __uint_as_float(b);
}
#define FMA2(acc, a, b) asm("fma.rn.f32x2 %0, %1, %2, %0;" : "+l"(acc) : "l"(a), "l"(b))

// ---------------- single-tap FFMA2 GEMM body ---------------------------------
// out[b,n,co] (+)= sum_ci A[n][b,ci] * Wt'[ci][co]   [+ bias on tap 0]
// TAP: 0 -> A = x (native layout), 1 -> A = g_t1, 2 -> A = g_u.
// Block tile 256 rows (32 nodes x 8 batches) x 64 cols; K=64 in 4 chunks of 16,
// double-buffered (LDG next chunk overlaps FFMA2 of current).
#define KC    16
#define AST   258
template <int TAP, bool ACC>
__device__ __forceinline__ void gemm_tap(int gb,
                                         const float* __restrict__ x,
                                         const float* __restrict__ bias,
                                         float* __restrict__ out) {
    __shared__ float As[2][KC * AST];   // 2 x 16512 B
    __shared__ float Ws[2][KC * 64];    // 2 x  4096 B

    int tid = threadIdx.x;
    int tx  = tid & 31;
    int wp  = tid >> 5;
    int n0  = gb * 32;

    int s_ci = tid & 15;
    int s_b  = (tid >> 4) & 7;
    int s_h  = tid >> 7;

    float  a_pref[16];
    float4 w_pref;

    auto prefetch = [&](int kc) {
        int koff = kc * KC;
        w_pref = __ldg((const float4*)(g_wt + TAP * 4096 + koff * 64) + tid);
        #pragma unroll
        for (int d = 0; d < 16; d++) {
            int n = n0 + s_h * 16 + d;
            if (n >= NN) n = NN - 1;
            if (TAP == 0)
                a_pref[d] = __ldg(&x[((size_t)s_b * NN + n) * 64 + koff + s_ci]);
            else {
                const float* src = (TAP == 1) ? g_t1 : g_u;
                a_pref[d] = __ldg(&src[(size_t)n * FF + s_b * 64 + koff + s_ci]);
            }
        }
    };
    auto store_stage = [&](int buf) {
        ((float4*)Ws[buf])[tid] = w_pref;
        #pragma unroll
        for (int d = 0; d < 16; d++) {
            int dn = s_h * 16 + d;
            As[buf][s_ci * AST + dn * 8 + s_b] = a_pref[d];
        }
    };

    unsigned long long acc[4][8];
    #pragma unroll
    for (int i = 0; i < 4; i++)
        #pragma unroll
        for (int j = 0; j < 8; j++) acc[i][j] = 0ULL;

    prefetch(0);
    store_stage(0);
    __syncthreads();

    #pragma unroll 1
    for (int kc = 0; kc < 4; kc++) {
        int cb = kc & 1;
        if (kc < 3) prefetch(kc + 1);

        #pragma unroll 4
        for (int kk = 0; kk < KC; kk++) {
            const float4* wrow = (const float4*)(Ws[cb] + kk * 64 + wp * 8);
            float4 wa = wrow[0], wb = wrow[1];
            unsigned long long wd[8];
            wd[0] = pack2(wa.x); wd[1] = pack2(wa.y);
            wd[2] = pack2(wa.z); wd[3] = pack2(wa.w);
            wd[4] = pack2(wb.x); wd[5] = pack2(wb.y);
            wd[6] = pack2(wb.z); wd[7] = pack2(wb.w);
            #pragma unroll
            for (int jp = 0; jp < 4; jp++) {
                unsigned long long ap =
                    *(const unsigned long long*)(As[cb] + kk * AST + jp * 64 + 2 * tx);
                #pragma unroll
                for (int c = 0; c < 8; c++) FMA2(acc[jp][c], ap, wd[c]);
            }
        }

        if (kc < 3) store_stage(cb ^ 1);
        __syncthreads();
    }

    // epilogue
    float bvs[8];
    if (!ACC) {
        float4 b0 = *(const float4*)(bias + wp * 8);
        float4 b1 = *(const float4*)(bias + wp * 8 + 4);
        bvs[0]=b0.x; bvs[1]=b0.y; bvs[2]=b0.z; bvs[3]=b0.w;
        bvs[4]=b1.x; bvs[5]=b1.y; bvs[6]=b1.z; bvs[7]=b1.w;
    }
    #pragma unroll
    for (int jp = 0; jp < 4; jp++) {
        int m0 = jp * 64 + 2 * tx;
        int dn = m0 >> 3;
        int n  = n0 + dn;
        if (n >= NN) continue;
        int b  = m0 & 7;
        float lo[8], hi[8];
        #pragma unroll
        for (int c = 0; c < 8; c++) unpack2(acc[jp][c], lo[c], hi[c]);
        float* p0 = out + ((size_t)b * NN + n) * 64 + wp * 8;
        float* p1 = out + ((size_t)(b + 1) * NN + n) * 64 + wp * 8;
        float4 o0, o1, o2, o3;
        if (ACC) {
            o0 = *(float4*)p0;       o1 = *(float4*)(p0 + 4);
            o2 = *(float4*)p1;       o3 = *(float4*)(p1 + 4);
            o0.x += lo[0]; o0.y += lo[1]; o0.z += lo[2]; o0.w += lo[3];
            o1.x += lo[4]; o1.y += lo[5]; o1.z += lo[6]; o1.w += lo[7];
            o2.x += hi[0]; o2.y += hi[1]; o2.z += hi[2]; o2.w += hi[3];
            o3.x += hi[4]; o3.y += hi[5]; o3.z += hi[6]; o3.w += hi[7];
        } else {
            o0.x = lo[0]+bvs[0]; o0.y = lo[1]+bvs[1]; o0.z = lo[2]+bvs[2]; o0.w = lo[3]+bvs[3];
            o1.x = lo[4]+bvs[4]; o1.y = lo[5]+bvs[5]; o1.z = lo[6]+bvs[6]; o1.w = lo[7]+bvs[7];
            o2.x = hi[0]+bvs[0]; o2.y = hi[1]+bvs[1]; o2.z = hi[2]+bvs[2]; o2.w = hi[3]+bvs[3];
            o3.x = hi[4]+bvs[4]; o3.y = hi[5]+bvs[5]; o3.z = hi[6]+bvs[6]; o3.w = hi[7]+bvs[7];
        }
        *(float4*)p0 = o0; *(float4*)(p0 + 4) = o1;
        *(float4*)p1 = o2; *(float4*)(p1 + 4) = o3;
    }
}

// ---------------- fat kernels: SpMM blocks + GEMM blocks in one grid ---------
// gemm blocks are bids with bid%5==2 (exactly GEMM_BLOCKS of FAT_BLOCKS);
// spmm index = bid - floor((bid+2)/5) in [0, SPMM_BLOCKS).
__global__ void __launch_bounds__(256, 2) k_fat1(const float* __restrict__ x,
                                                  const float* __restrict__ bias,
                                                  float* __restrict__ out) {
    int bid = blockIdx.x;
    if (bid % 5 == 2) {
        gemm_tap<0, false>(bid / 5, x, bias, out);   // out = bias + x*(W0-W2)
    } else {
        int sidx = bid - (bid + 2) / 5;
        int gw   = sidx * 8 + (threadIdx.x >> 5);
        if (gw < NN) spmm0_body(gw, threadIdx.x & 31, x);   // t1 = L @ x
    }
}

__global__ void __launch_bounds__(256, 2) k_fat2(const float* __restrict__ x,
                                                  const float* __restrict__ bias,
                                                  float* __restrict__ out) {
    int bid = blockIdx.x;
    if (bid % 5 == 2) {
        gemm_tap<1, true>(bid / 5, x, bias, out);    // out += t1*W1
    } else {
        int sidx = bid - (bid + 2) / 5;
        int gw   = sidx * 8 + (threadIdx.x >> 5);
        if (gw < NN) spmm1_body(gw, threadIdx.x & 31);      // u = L @ t1
    }
}

__global__ void __launch_bounds__(256, 2) k_tap2(const float* __restrict__ x,
                                                  const float* __restrict__ bias,
                                                  float* __restrict__ out) {
    gemm_tap<2, true>(blockIdx.x, x, bias, out);     // out += u*(2*W2)
}

// ---------------- launch ----------------------------------------------------
extern "C" void kernel_launch(void* const* d_in, const int* in_sizes, int n_in,
                              void* d_out, int out_size) {
    const float* x    = (const float*)d_in[0];   // [8, 50000, 64] f32
    const float* wgt  = (const float*)d_in[1];   // [3, 64, 64]    f32
    const float* bias = (const float*)d_in[2];   // [64]           f32
    const void*  ei   = d_in[3];                 // [2, 400000] int64 or int32
    float* out = (float*)d_out;                  // [8, 50000, 64] f32

    k_setup1<<<(NN + 255) / 256, 256>>>(ei, wgt);
    k_count<<<(EE + 255) / 256, 256>>>(ei);
    k_setup2<<<(NN + 255) / 256, 256>>>();
    k_fill<<<(EE + 255) / 256, 256>>>(ei);
    k_fat1<<<FAT_BLOCKS, 256>>>(x, bias, out);
    k_fat2<<<FAT_BLOCKS, 256>>>(x, bias, out);
    k_tap2<<<GEMM_BLOCKS, 256>>>(x, bias, out);
}

// round 17
// speedup vs baseline: 1.6558x; 1.6558x over previous
#include <cuda_runtime.h>
#include <cstdint>

// FixBatchChebConv: B=8, N=50000, Cin=Cout=64, K=3, E=400000
#define BB    8
#define NN    50000
#define EE    400000
#define FF    512           // BB*64, features per node in transposed layout
#define FF4   (FF/4)

// ---------------- scratch (static device globals; no runtime allocation) ----
__device__ float g_t1[(size_t)NN * FF];   // tx1 = L @ x    (transposed [n][512])
__device__ float g_u [(size_t)NN * FF];   // u   = L @ tx1  (t2 = 2u - x folded into W)
__device__ float g_wt[12288];             // folded weights: [W0-W2 | W1 | 2*W2], [k(192)][co(64)]
__device__ uint32_t g_wbh[6144];          // W hi bf16, FRAGMENT layout [kstep12][ntile8][reg2][lane32]
__device__ uint32_t g_wbl[6144];          // W lo bf16, same layout
__device__ int   g_deg[NN];
__device__ int   g_rowstart[NN];
__device__ int   g_fill[NN];
__device__ float g_dinv[NN];
__device__ int   g_col[EE];
__device__ float g_lap[EE];
__device__ int   g_total;
__device__ int   g_is64;

// ---------------- setup kernels (R14, proven) --------------------------------
__global__ void k_setup1(const void* ei, const float* __restrict__ wgt) {
    int n = blockIdx.x * blockDim.x + threadIdx.x;
    if (n < NN) { g_deg[n] = 0; g_fill[n] = 0; }
    if (n == 0) g_total = 0;
    if (n < 12288) {
        int t = n >> 12;                 // 0..2
        float w = wgt[n];
        if (t == 0)      w = w - wgt[n + 8192];   // W0 - W2
        else if (t == 2) w = 2.0f * w;            // 2*W2
        g_wt[n] = w;
    }
    if (blockIdx.x == 0 && threadIdx.x < 64) {
        const long long* p = (const long long*)ei;
        long long v = p[threadIdx.x];
        int ok = (v >= 0 && v < NN) ? 1 : 0;
        unsigned m0 = __ballot_sync(0xffffffffu, ok);
        __shared__ unsigned warp_ok[2];
        if ((threadIdx.x & 31) == 0) warp_ok[threadIdx.x >> 5] = m0;
        __syncthreads();
        if (threadIdx.x == 0)
            g_is64 = (warp_ok[0] == 0xffffffffu && warp_ok[1] == 0xffffffffu) ? 1 : 0;
    }
}

__device__ __forceinline__ void load_edge(const void* ei, int e, int& r, int& c) {
    if (g_is64) {
        const long long* p = (const long long*)ei;
        r = (int)p[e]; c = (int)p[EE + e];
    } else {
        const int* p = (const int*)ei;
        r = p[e]; c = p[EE + e];
    }
}

__global__ void k_count(const void* ei) {
    int e = blockIdx.x * blockDim.x + threadIdx.x;
    if (e >= EE) return;
    int r, c; load_edge(ei, e, r, c);
    if (r != c) atomicAdd(&g_deg[r], 1);
}

__global__ void k_setup2() {
    int n = blockIdx.x * blockDim.x + threadIdx.x;
    int lane = threadIdx.x & 31;
    int d = (n < NN) ? g_deg[n] : 0;
    if (n < NN) g_dinv[n] = (d > 0) ? rsqrtf((float)d) : 0.0f;
    int incl = d;
    #pragma unroll
    for (int o = 1; o < 32; o <<= 1) {
        int y = __shfl_up_sync(0xffffffffu, incl, o);
        if (lane >= o) incl += y;
    }
    int tot = __shfl_sync(0xffffffffu, incl, 31);
    int base = 0;
    if (lane == 0) base = atomicAdd(&g_total, tot);
    base = __shfl_sync(0xffffffffu, base, 0);
    if (n < NN) g_rowstart[n] = base + incl - d;
}

__global__ void k_fill(const void* ei) {
    int e = blockIdx.x * blockDim.x + threadIdx.x;
    if (e >= EE) return;
    int r, c; load_edge(ei, e, r, c);
    if (r != c) {
        int pos = atomicAdd(&g_fill[r], 1);
        int idx = g_rowstart[r] + pos;
        g_col[idx] = c;
        g_lap[idx] = -g_dinv[r] * g_dinv[c];
    }
}

// pack (f0 -> low half, f1 -> high half) bf16x2
__device__ __forceinline__ uint32_t cvt_bf2(float f0, float f1) {
    uint32_t r;
    asm("cvt.rn.satfinite.bf16x2.f32 %0, %1, %2;" : "=r"(r) : "f"(f1), "f"(f0));
    return r;
}

// W prep: split folded weights to bf16 hi/lo and write in mma B-fragment layout:
//   slot [kstep][ntile][reg][lane]: tig=lane&3, g=lane>>2, n=ntile*8+g,
//   k = kstep*16 + tig*2 + reg*8, value = {W(k,n) lo half, W(k+1,n) hi half}.
__global__ void k_prep() {
    for (int idx = threadIdx.x; idx < 6144; idx += blockDim.x) {
        int lane  = idx & 31;
        int reg   = (idx >> 5) & 1;
        int nt    = (idx >> 6) & 7;
        int kstep = idx >> 9;
        int tig = lane & 3, g = lane >> 2;
        int n = nt * 8 + g;
        int k = kstep * 16 + tig * 2 + reg * 8;
        float w1 = g_wt[k * 64 + n];
        float w2 = g_wt[(k + 1) * 64 + n];
        uint32_t h = cvt_bf2(w1, w2);
        float h1 = __uint_as_float(h << 16);
        float h2 = __uint_as_float(h & 0xFFFF0000u);
        uint32_t l = cvt_bf2(w1 - h1, w2 - h2);
        g_wbh[idx] = h;
        g_wbl[idx] = l;
    }
}

// ---------------- spmm kernels (R14, proven) ---------------------------------
__global__ void k_spmm0(const float* __restrict__ x) {
    int gw   = (blockIdx.x * blockDim.x + threadIdx.x) >> 5;
    int lane = threadIdx.x & 31;
    if (gw >= NN) return;
    int s = g_rowstart[gw];
    int e = s + g_deg[gw];
    int c4 = lane & 15;
    int b0 = lane >> 4;
    float4 acc[4];
    #pragma unroll
    for (int q = 0; q < 4; q++) acc[q] = make_float4(0.f, 0.f, 0.f, 0.f);
    const float4* xv = (const float4*)x;
    for (int i = s; i < e; i++) {
        int   c = g_col[i];
        float w = g_lap[i];
        #pragma unroll
        for (int q = 0; q < 4; q++) {
            float4 v = __ldg(&xv[((size_t)(b0 + q * 2) * NN + c) * 16 + c4]);
            acc[q].x += w * v.x; acc[q].y += w * v.y;
            acc[q].z += w * v.z; acc[q].w += w * v.w;
        }
    }
    float4* dstv = (float4*)g_t1;
    size_t o0 = (size_t)gw * FF4 + lane;
    #pragma unroll
    for (int q = 0; q < 4; q++) dstv[o0 + q * 32] = acc[q];
}

__global__ void k_spmm1() {
    int gw   = (blockIdx.x * blockDim.x + threadIdx.x) >> 5;
    int lane = threadIdx.x & 31;
    if (gw >= NN) return;
    int s = g_rowstart[gw];
    int e = s + g_deg[gw];
    float4 acc[4];
    #pragma unroll
    for (int q = 0; q < 4; q++) acc[q] = make_float4(0.f, 0.f, 0.f, 0.f);
    const float4* srcv = (const float4*)g_t1;
    for (int i = s; i < e; i++) {
        int   c = g_col[i];
        float w = g_lap[i];
        size_t b0 = (size_t)c * FF4 + lane;
        #pragma unroll
        for (int q = 0; q < 4; q++) {
            float4 v = __ldg(&srcv[b0 + q * 32]);
            acc[q].x += w * v.x; acc[q].y += w * v.y;
            acc[q].z += w * v.z; acc[q].w += w * v.w;
        }
    }
    float4* dstv = (float4*)g_u;
    size_t o0 = (size_t)gw * FF4 + lane;
    #pragma unroll
    for (int q = 0; q < 4; q++) dstv[o0 + q * 32] = acc[q];
}

// ---------------- HMMA GEMM --------------------------------------------------
// out[b,n,co] = bias[co] + sum_k A[k-tap][n][b,k] * Wfold[k][co], K=192, via
// mma.sync m16n8k16 bf16 with 3-term split (Ah*Wh + Ah*Wl + Al*Wh), fp32 acc.
// Block: 32 nodes -> 256 rows (m = dn*8+b) x 64 cols. 8 warps; warp owns
// mtiles {2w, 2w+1} (32 rows) x all 8 ntiles. Fragments pre-arranged in smem
// slots [kstep][mtile][reg][lane] (bank=lane -> STS/LDS conflict-free).
__device__ __forceinline__ void mma16816(float* d, const uint32_t* a,
                                         uint32_t b0, uint32_t b1) {
    asm volatile(
        "mma.sync.aligned.m16n8k16.row.col.f32.bf16.bf16.f32 "
        "{%0,%1,%2,%3}, {%4,%5,%6,%7}, {%8,%9}, {%0,%1,%2,%3};"
        : "+f"(d[0]), "+f"(d[1]), "+f"(d[2]), "+f"(d[3])
        : "r"(a[0]), "r"(a[1]), "r"(a[2]), "r"(a[3]), "r"(b0), "r"(b1));
}

#define SA_WORDS 4096      // A plane: 2 ksteps x 16 mtiles x 4 regs x 32 lanes
#define SB_WORDS 6144      // B plane: 12 ksteps x 8 ntiles x 2 regs x 32 lanes
#define HSMEM    ((2 * SA_WORDS + 2 * SB_WORDS) * 4)   // 81920 B

__global__ void __launch_bounds__(256, 2) k_hmma(const float* __restrict__ x,
                                                 const float* __restrict__ bias,
                                                 float* __restrict__ out) {
    extern __shared__ uint32_t sh[];
    uint32_t* sAh = sh;
    uint32_t* sAl = sAh + SA_WORDS;
    uint32_t* sBh = sAl + SA_WORDS;
    uint32_t* sBl = sBh + SB_WORDS;

    int tid  = threadIdx.x;
    int lane = tid & 31;
    int wid  = tid >> 5;
    int n0   = blockIdx.x * 32;

    // ---- stage W fragments (linear 48KB copy) ----
    {
        const uint4* srch = (const uint4*)g_wbh;
        const uint4* srcl = (const uint4*)g_wbl;
        uint4* dsth = (uint4*)sBh;
        uint4* dstl = (uint4*)sBl;
        #pragma unroll
        for (int i = 0; i < 6; i++) {      // 1536 uint4 per plane
            int j = tid + i * 256;
            dsth[j] = __ldg(&srch[j]);
            dstl[j] = __ldg(&srcl[j]);
        }
    }

    float acc[2][8][4];
    #pragma unroll
    for (int i = 0; i < 2; i++)
        #pragma unroll
        for (int j = 0; j < 8; j++)
            #pragma unroll
            for (int q = 0; q < 4; q++) acc[i][j][q] = 0.0f;

    int g   = lane >> 2;     // groupID
    int tig = lane & 3;

    #pragma unroll 1
    for (int kc = 0; kc < 6; kc++) {       // 6 chunks of K=32
        __syncthreads();                   // prev compute done before overwrite

        // ---- stage A chunk: warp w covers mtiles {2w, 2w+1} ----
        {
            int tap  = kc >> 1;            // 0:x  1:t1  2:u
            int cio  = (kc & 1) * 32;      // ci offset within tap
            #pragma unroll
            for (int mt2 = 0; mt2 < 2; mt2++) {
                int mtile = wid * 2 + mt2;
                #pragma unroll
                for (int ks = 0; ks < 2; ks++) {
                    #pragma unroll
                    for (int r = 0; r < 4; r++) {
                        int m  = mtile * 16 + (r & 1) * 8 + g;
                        int kl = ks * 16 + ((r >> 1) * 8) + tig * 2;
                        int n  = n0 + (m >> 3);
                        if (n >= NN) n = NN - 1;
                        int b  = m & 7;
                        float2 v;
                        if (tap == 0)
                            v = *(const float2*)&x[((size_t)b * NN + n) * 64 + cio + kl];
                        else {
                            const float* src = (tap == 1) ? g_t1 : g_u;
                            v = *(const float2*)&src[(size_t)n * FF + b * 64 + cio + kl];
                        }
                        uint32_t h = cvt_bf2(v.x, v.y);
                        float h1 = __uint_as_float(h << 16);
                        float h2 = __uint_as_float(h & 0xFFFF0000u);
                        uint32_t l = cvt_bf2(v.x - h1, v.y - h2);
                        int widx = ((ks * 16 + mtile) * 4 + r) * 32 + lane;
                        sAh[widx] = h;
                        sAl[widx] = l;
                    }
                }
            }
        }
        __syncthreads();

        // ---- compute: 2 ksteps x 8 ntiles x 2 mtiles x 3 split terms ----
        #pragma unroll
        for (int ks = 0; ks < 2; ks++) {
            uint32_t ah[2][4], al[2][4];
            #pragma unroll
            for (int mt2 = 0; mt2 < 2; mt2++)
                #pragma unroll
                for (int r = 0; r < 4; r++) {
                    int widx = ((ks * 16 + wid * 2 + mt2) * 4 + r) * 32 + lane;
                    ah[mt2][r] = sAh[widx];
                    al[mt2][r] = sAl[widx];
                }
            int ksg = kc * 2 + ks;         // global kstep 0..11
            #pragma unroll
            for (int nt = 0; nt < 8; nt++) {
                int bidx = ((ksg * 8 + nt) * 2) * 32 + lane;
                uint32_t bh0 = sBh[bidx], bh1 = sBh[bidx + 32];
                uint32_t bl0 = sBl[bidx], bl1 = sBl[bidx + 32];
                #pragma unroll
                for (int mt2 = 0; mt2 < 2; mt2++) {
                    mma16816(acc[mt2][nt], ah[mt2], bh0, bh1);
                    mma16816(acc[mt2][nt], ah[mt2], bl0, bl1);
                    mma16816(acc[mt2][nt], al[mt2], bh0, bh1);
                }
            }
        }
    }

    // ---- epilogue: bias + store ----
    #pragma unroll
    for (int mt2 = 0; mt2 < 2; mt2++) {
        int mtile = wid * 2 + mt2;
        #pragma unroll
        for (int half = 0; half < 2; half++) {
            int m = mtile * 16 + half * 8 + g;
            int n = n0 + (m >> 3);
            if (n >= NN) continue;
            int b = m & 7;
            float* po = out + ((size_t)b * NN + n) * 64;
            #pragma unroll
            for (int nt = 0; nt < 8; nt++) {
                int col = nt * 8 + tig * 2;
                float2 bv = *(const float2*)&bias[col];
                float2 o;
                o.x = acc[mt2][nt][half * 2 + 0] + bv.x;
                o.y = acc[mt2][nt][half * 2 + 1] + bv.y;
                *(float2*)(po + col) = o;
            }
        }
    }
}

// ---------------- launch ----------------------------------------------------
extern "C" void kernel_launch(void* const* d_in, const int* in_sizes, int n_in,
                              void* d_out, int out_size) {
    const float* x    = (const float*)d_in[0];   // [8, 50000, 64] f32
    const float* wgt  = (const float*)d_in[1];   // [3, 64, 64]    f32
    const float* bias = (const float*)d_in[2];   // [64]           f32
    const void*  ei   = d_in[3];                 // [2, 400000] int64 or int32
    float* out = (float*)d_out;                  // [8, 50000, 64] f32

    cudaFuncSetAttribute(k_hmma, cudaFuncAttributeMaxDynamicSharedMemorySize,
                         HSMEM);

    k_setup1<<<(NN + 255) / 256, 256>>>(ei, wgt);
    k_count<<<(EE + 255) / 256, 256>>>(ei);
    k_setup2<<<(NN + 255) / 256, 256>>>();
    k_fill<<<(EE + 255) / 256, 256>>>(ei);
    k_prep<<<1, 256>>>();
    k_spmm0<<<(NN * 32 + 255) / 256, 256>>>(x);
    k_spmm1<<<(NN * 32 + 255) / 256, 256>>>();
    k_hmma<<<(NN + 31) / 32, 256, HSMEM>>>(x, bias, out);
}